// round 1
// baseline (speedup 1.0000x reference)
#include <cuda_runtime.h>
#include <cuda_bf16.h>

#define B_SZ   512
#define N_SZ   1024
#define D_SZ   128
#define CHUNK  128
#define NCHUNK (N_SZ / CHUNK)   // 8
#define H1D    128
#define H2D    64
#define NOUT   (N_SZ - 1)       // 1023

#define LDA 132                 // padded tok-stride for [k][tok] arrays
#define LDW 132                 // padded out-stride for [k][out] arrays
#define LDH2 129                // stride for H2s [out2][tok]

// smem float offsets
#define XS_OFF 0                // 128*128 = 16384  (raw chunk [n][d]; later H2s)
#define AS_OFF 16384            // 128*132 = 16896  (CS^T [k][tok]; later H1s [out1][tok])
#define WS_OFF 33280            // 128*132 = 16896  (W1^T [k][out]; later W2^T)
#define B1_OFF 50176            // 128
#define B2_OFF 50304            // 64
#define W3_OFF 50368            // 64
#define B3_OFF 50432            // 1
#define SMEM_FLOATS 50436
#define SMEM_BYTES  (SMEM_FLOATS * 4)

// chunk carries: carry[b][c][d] = sum_{n < c*CHUNK} x[b][n][d]
__device__ float g_carry[B_SZ * NCHUNK * D_SZ];

// ---------------------------------------------------------------------------
// Kernel 1: per-chunk carries (one 256MB streaming pass, mem-bound)
// ---------------------------------------------------------------------------
__global__ void carry_kernel(const float* __restrict__ x) {
    int b = blockIdx.x;
    int d = threadIdx.x;            // 128 threads, one per dim
    const float* xb = x + ((size_t)b * N_SZ) * D_SZ + d;
    float run = 0.f;
#pragma unroll
    for (int c = 0; c < NCHUNK; ++c) {
        g_carry[((size_t)b * NCHUNK + c) * D_SZ + d] = run;
        const float* xc = xb + (size_t)c * CHUNK * D_SZ;
        float s0 = 0.f, s1 = 0.f, s2 = 0.f, s3 = 0.f;
#pragma unroll 8
        for (int n = 0; n < CHUNK; n += 4) {
            s0 += xc[(n + 0) * D_SZ];
            s1 += xc[(n + 1) * D_SZ];
            s2 += xc[(n + 2) * D_SZ];
            s3 += xc[(n + 3) * D_SZ];
        }
        run += (s0 + s1) + (s2 + s3);
    }
}

// ---------------------------------------------------------------------------
// Kernel 2: fused scan + 3-layer MLP per (batch, chunk)
// ---------------------------------------------------------------------------
__global__ void __launch_bounds__(256, 1) mlp_kernel(
    const float* __restrict__ x,
    const float* __restrict__ W1, const float* __restrict__ b1,
    const float* __restrict__ W2, const float* __restrict__ b2,
    const float* __restrict__ W3, const float* __restrict__ b3,
    float* __restrict__ out)
{
    extern __shared__ float sm[];
    float* Xs  = sm + XS_OFF;   // chunk staging [n][d] (128x128)
    float* As  = sm + AS_OFF;   // [k][tok], stride LDA
    float* Ws  = sm + WS_OFF;   // [k][out], stride LDW
    float* b1s = sm + B1_OFF;
    float* b2s = sm + B2_OFF;
    float* W3s = sm + W3_OFF;
    float* b3s = sm + B3_OFF;

    const int tid = threadIdx.x;
    const int b   = blockIdx.x >> 3;   // batch
    const int c   = blockIdx.x & 7;    // chunk

    // ---- P0: stage raw chunk + W1^T + biases --------------------------------
    const float* xc = x + ((size_t)b * N_SZ + (size_t)c * CHUNK) * D_SZ;
    {
        const float4* src = (const float4*)xc;
        float4* dst = (float4*)Xs;
#pragma unroll
        for (int i = 0; i < 16; ++i)                 // 16384 floats
            dst[tid + i * 256] = src[tid + i * 256];
    }
    {
#pragma unroll
        for (int i = 0; i < 64; ++i) {               // W1: 16384 floats
            int idx = tid + i * 256;
            int o = idx >> 7, k = idx & 127;
            Ws[k * LDW + o] = W1[idx];               // transpose to [k][out]
        }
    }
    if (tid < 128)      b1s[tid] = b1[tid];
    else if (tid < 192) b2s[tid - 128] = b2[tid - 128];
    else                W3s[tid - 192] = W3[tid - 192];
    if (tid == 0) b3s[0] = b3[0];
    __syncthreads();

    // ---- P1: scan (inclusive prefix + carry), write k-major -----------------
    if (tid < 128) {
        const int d = tid;
        float s = g_carry[((size_t)b * NCHUNK + c) * D_SZ + d];
#pragma unroll 16
        for (int n = 0; n < CHUNK; ++n) {
            s += Xs[n * 128 + d];
            As[d * LDA + n] = s;
        }
    }
    __syncthreads();

    const int tx = tid & 15;        // 16 output-tile groups
    const int ty = tid >> 4;        // 16 token-tile groups

    // ---- P2: GEMM1  H1 = leaky(CS @ W1^T + b1)  (128x128x128) --------------
    float c1[8][8];
#pragma unroll
    for (int i = 0; i < 8; ++i)
#pragma unroll
        for (int j = 0; j < 8; ++j) c1[i][j] = 0.f;

#pragma unroll 2
    for (int k = 0; k < 128; ++k) {
        float4 a0 = *(const float4*)(As + k * LDA + ty * 8);
        float4 a1 = *(const float4*)(As + k * LDA + ty * 8 + 4);
        float4 w0 = *(const float4*)(Ws + k * LDW + tx * 8);
        float4 w1 = *(const float4*)(Ws + k * LDW + tx * 8 + 4);
        float av[8] = {a0.x, a0.y, a0.z, a0.w, a1.x, a1.y, a1.z, a1.w};
        float wv[8] = {w0.x, w0.y, w0.z, w0.w, w1.x, w1.y, w1.z, w1.w};
#pragma unroll
        for (int i = 0; i < 8; ++i)
#pragma unroll
            for (int j = 0; j < 8; ++j)
                c1[i][j] += av[i] * wv[j];
    }
    __syncthreads();   // all reads of As/Ws complete

    // bias + leaky, write H1 -> As as [out1][tok] (jj-rotation vs banks)
#pragma unroll
    for (int j = 0; j < 8; ++j) {
        int jj = (j + tx) & 7;
        int o  = tx * 8 + jj;
        float bb = b1s[o];
#pragma unroll
        for (int i = 0; i < 8; ++i) {
            float v = c1[i][jj] + bb;
            v = v > 0.f ? v : 0.01f * v;
            As[o * LDA + ty * 8 + i] = v;
        }
    }
    // load W2^T -> Ws  (W2 is [64][128])
#pragma unroll
    for (int i = 0; i < 32; ++i) {                   // 8192 floats
        int idx = tid + i * 256;
        int o = idx >> 7, k = idx & 127;
        Ws[k * LDW + o] = W2[idx];
    }
    __syncthreads();

    // ---- P4: GEMM2  H2 = leaky(H1 @ W2^T + b2)  (128x64x128) ---------------
    float c2[8][4];
#pragma unroll
    for (int i = 0; i < 8; ++i)
#pragma unroll
        for (int j = 0; j < 4; ++j) c2[i][j] = 0.f;

#pragma unroll 2
    for (int k = 0; k < 128; ++k) {
        float4 a0 = *(const float4*)(As + k * LDA + ty * 8);
        float4 a1 = *(const float4*)(As + k * LDA + ty * 8 + 4);
        float4 w  = *(const float4*)(Ws + k * LDW + tx * 4);
        float av[8] = {a0.x, a0.y, a0.z, a0.w, a1.x, a1.y, a1.z, a1.w};
        float wv[4] = {w.x, w.y, w.z, w.w};
#pragma unroll
        for (int i = 0; i < 8; ++i)
#pragma unroll
            for (int j = 0; j < 4; ++j)
                c2[i][j] += av[i] * wv[j];
    }
    __syncthreads();   // reads of As done before overwriting Xs region is fine; Xs free since P1

    // bias + leaky, write H2 -> Xs region as [out2][tok], stride LDH2
    float* H2s = Xs;
#pragma unroll
    for (int j = 0; j < 4; ++j) {
        int jj = (j + tx) & 3;
        int o  = tx * 4 + jj;
        float bb = b2s[o];
#pragma unroll
        for (int i = 0; i < 8; ++i) {
            float v = c2[i][jj] + bb;
            v = v > 0.f ? v : 0.01f * v;
            H2s[o * LDH2 + ty * 8 + i] = v;
        }
    }
    __syncthreads();

    // ---- P6: GEMM3  out = H2 @ W3^T + b3  (64-dot per token) ---------------
    if (tid < 128) {
        const int t = tid;
        float acc = b3s[0];
#pragma unroll
        for (int j = 0; j < 64; ++j)
            acc += H2s[j * LDH2 + t] * W3s[j];
        int g = c * CHUNK + t;               // global cumsum index
        if (g > 0)
            out[(size_t)b * NOUT + (g - 1)] = acc;
    }
}

// ---------------------------------------------------------------------------
extern "C" void kernel_launch(void* const* d_in, const int* in_sizes, int n_in,
                              void* d_out, int out_size) {
    const float* x  = (const float*)d_in[0];
    const float* W1 = (const float*)d_in[1];
    const float* b1 = (const float*)d_in[2];
    const float* W2 = (const float*)d_in[3];
    const float* b2 = (const float*)d_in[4];
    const float* W3 = (const float*)d_in[5];
    const float* b3 = (const float*)d_in[6];
    float* out = (float*)d_out;

    static bool attr_done = false;
    if (!attr_done) {
        cudaFuncSetAttribute(mlp_kernel,
                             cudaFuncAttributeMaxDynamicSharedMemorySize,
                             SMEM_BYTES);
        attr_done = true;
    }

    carry_kernel<<<B_SZ, 128>>>(x);
    mlp_kernel<<<B_SZ * NCHUNK, 256, SMEM_BYTES>>>(x, W1, b1, W2, b2, W3, b3, out);
}

// round 4
// speedup vs baseline: 2.5553x; 2.5553x over previous
#include <cuda_runtime.h>
#include <cuda_bf16.h>
#include <stdint.h>
#include <string.h>

#define BATCH  512
#define NTOK   1024
#define DDIM   128
#define NCHUNK 8
#define NOUT   1023

// ---------------- smem layout (bytes) ----------------
#define S_STAGE 0             // 57344: fp32 x chunk rows 0..111
#define S_AHI   57344         // 32768: A/H1 hi bf16 [128 rows][256B]
#define S_ALO   90112         // 32768
#define S_W1HI  122880        // 32768
#define S_W1LO  155648        // 32768
#define S_W2HI  188416        // 16384: [64 rows][256B]
#define S_W2LO  204800        // 16384
#define S_TOT   221184        // 4096: warp totals [8][128] f32
#define S_OFF   225280        // 4096: per-warp offsets [8][128] f32
#define S_B1    229376        // 512
#define S_CC    229888        // 512
#define S_B2    230400        // 256
#define S_W3    230656        // 256
#define S_B3    230912        // 16
#define SMEM_BYTES 230928

static __device__ __forceinline__ uint32_t smem_u32(const void* p) {
    uint32_t a;
    asm("{ .reg .u64 t; cvta.to.shared.u64 t, %1; cvt.u32.u64 %0, t; }"
        : "=r"(a) : "l"(p));
    return a;
}
// tile addr: 256B rows, XOR-swizzle 16B groups by row%8
static __device__ __forceinline__ uint32_t tswz(uint32_t row, uint32_t cb) {
    return row * 256 + (cb ^ ((row & 7) << 4));
}
static __device__ __forceinline__ float bfr(float v) {
    return __bfloat162float(__float2bfloat16(v));
}
static __device__ __forceinline__ uint32_t pack2(float a, float b) {
    __nv_bfloat162 h = __floats2bfloat162_rn(a, b);
    uint32_t u;
    memcpy(&u, &h, 4);
    return u;
}
static __device__ __forceinline__ float lrelu(float v) {
    return v > 0.f ? v : 0.01f * v;
}
static __device__ __forceinline__ void ldm4(uint32_t addr, uint32_t& r0, uint32_t& r1,
                                            uint32_t& r2, uint32_t& r3) {
    asm volatile("ldmatrix.sync.aligned.m8n8.x4.shared.b16 {%0,%1,%2,%3}, [%4];"
                 : "=r"(r0), "=r"(r1), "=r"(r2), "=r"(r3) : "r"(addr));
}
static __device__ __forceinline__ void mma16816(float* d, uint32_t a0, uint32_t a1,
                                                uint32_t a2, uint32_t a3,
                                                uint32_t b0, uint32_t b1) {
    asm volatile("mma.sync.aligned.m16n8k16.row.col.f32.bf16.bf16.f32 "
                 "{%0,%1,%2,%3}, {%4,%5,%6,%7}, {%8,%9}, {%0,%1,%2,%3};"
                 : "+f"(d[0]), "+f"(d[1]), "+f"(d[2]), "+f"(d[3])
                 : "r"(a0), "r"(a1), "r"(a2), "r"(a3), "r"(b0), "r"(b1));
}
static __device__ __forceinline__ void scan_col(float& lo, float& hi, int lane) {
    float o;
    o = __shfl_up_sync(0xffffffffu, lo, 4);  if (lane >= 4)  lo += o;
    o = __shfl_up_sync(0xffffffffu, lo, 8);  if (lane >= 8)  lo += o;
    o = __shfl_up_sync(0xffffffffu, lo, 16); if (lane >= 16) lo += o;
    float tl = __shfl_sync(0xffffffffu, lo, 28 + (lane & 3));
    o = __shfl_up_sync(0xffffffffu, hi, 4);  if (lane >= 4)  hi += o;
    o = __shfl_up_sync(0xffffffffu, hi, 8);  if (lane >= 8)  hi += o;
    o = __shfl_up_sync(0xffffffffu, hi, 16); if (lane >= 16) hi += o;
    hi += tl;
}

__global__ void __launch_bounds__(256, 1)
fused_kernel(const float* __restrict__ x,
             const float* __restrict__ W1, const float* __restrict__ b1,
             const float* __restrict__ W2, const float* __restrict__ b2,
             const float* __restrict__ W3, const float* __restrict__ b3,
             float* __restrict__ out)
{
    extern __shared__ char sm[];
    const uint32_t sb = smem_u32(sm);
    const int tid  = threadIdx.x;
    const int wid  = tid >> 5;
    const int lane = tid & 31;
    const int quad = lane >> 2;
    const int four = lane & 3;
    const int bb   = blockIdx.x;

    const float* xb = x + (size_t)bb * NTOK * DDIM;

    // ---- kick cp.async for chunk 0 (rows 0..111) + tail regs (112..127) ----
    float4 tl0, tl1;
    {
        const float4* s = (const float4*)xb;
#pragma unroll
        for (int i = 0; i < 14; ++i) {
            uint32_t d = sb + S_STAGE + (uint32_t)(tid + i * 256) * 16;
            asm volatile("cp.async.cg.shared.global [%0], [%1], 16;"
                         :: "r"(d), "l"(s + tid + i * 256) : "memory");
        }
        asm volatile("cp.async.commit_group;" ::: "memory");
        tl0 = s[3584 + tid];
        tl1 = s[3840 + tid];
    }

    // ---- stage weights: fp32 -> bf16 hi/lo swizzled tiles ----
    {
        const float2* w1 = (const float2*)W1;
#pragma unroll 4
        for (int i = 0; i < 32; ++i) {
            int idx = tid + i * 256;
            int n = idx >> 6, kp = idx & 63;
            float2 v = w1[idx];
            float hx = bfr(v.x), hy = bfr(v.y);
            uint32_t a = tswz(n, kp * 4);
            *(uint32_t*)(sm + S_W1HI + a) = pack2(hx, hy);
            *(uint32_t*)(sm + S_W1LO + a) = pack2(v.x - hx, v.y - hy);
        }
        const float2* w2 = (const float2*)W2;
#pragma unroll 4
        for (int i = 0; i < 16; ++i) {
            int idx = tid + i * 256;
            int n = idx >> 6, kp = idx & 63;
            float2 v = w2[idx];
            float hx = bfr(v.x), hy = bfr(v.y);
            uint32_t a = tswz(n, kp * 4);
            *(uint32_t*)(sm + S_W2HI + a) = pack2(hx, hy);
            *(uint32_t*)(sm + S_W2LO + a) = pack2(v.x - hx, v.y - hy);
        }
    }
    if (tid < 128) {
        ((float*)(sm + S_B1))[tid] = b1[tid];
        ((float*)(sm + S_CC))[tid] = 0.f;
    } else if (tid < 192) {
        ((float*)(sm + S_B2))[tid - 128] = b2[tid - 128];
    } else {
        ((float*)(sm + S_W3))[tid - 192] = W3[tid - 192];
    }
    if (tid == 0) *(float*)(sm + S_B3) = b3[0];

    // ldmatrix per-lane address pieces (XOR swizzle applied per k-step)
    const uint32_t xr   = (uint32_t)((lane & 7) << 4);
    const uint32_t aRow = (uint32_t)(16 * wid + (lane & 7) + ((lane >> 3) & 1) * 8) * 256;
    const uint32_t aCol = (uint32_t)(((lane >> 4) & 1) * 16);
    const uint32_t bRow = (uint32_t)((lane & 7) + ((lane >> 4) & 1) * 8) * 256;
    const uint32_t bCol = (uint32_t)(((lane >> 3) & 1) * 16);

    for (int c = 0; c < NCHUNK; ++c) {
        asm volatile("cp.async.wait_group 0;" ::: "memory");
        __syncthreads();

        // ---- convert staged chunk -> A hi/lo bf16 ----
        {
            const float2* stg = (const float2*)(sm + S_STAGE);
#pragma unroll 4
            for (int i = 0; i < 28; ++i) {       // rows 0..111
                int idx = tid + i * 256;
                float2 v = stg[idx];
                int t = idx >> 6, kp = idx & 63;
                float hx = bfr(v.x), hy = bfr(v.y);
                uint32_t a = tswz(t, kp * 4);
                *(uint32_t*)(sm + S_AHI + a) = pack2(hx, hy);
                *(uint32_t*)(sm + S_ALO + a) = pack2(v.x - hx, v.y - hy);
            }
            // tail rows 112..127 from registers
#pragma unroll
            for (int h = 0; h < 2; ++h) {
                float4 v = h ? tl1 : tl0;
                int j = tid + h * 256;
                int off = 14336 + j * 4;
                int r = off >> 7, cb = (off & 127) * 2;
                float h0 = bfr(v.x), h1 = bfr(v.y), h2 = bfr(v.z), h3 = bfr(v.w);
                uint32_t a = tswz(r, (uint32_t)cb);
                *(uint2*)(sm + S_AHI + a) = make_uint2(pack2(h0, h1), pack2(h2, h3));
                *(uint2*)(sm + S_ALO + a) = make_uint2(pack2(v.x - h0, v.y - h1),
                                                       pack2(v.z - h2, v.w - h3));
            }
        }
        __syncthreads();

        // ---- prefetch next chunk ----
        if (c + 1 < NCHUNK) {
            const float4* s = (const float4*)(xb + (size_t)(c + 1) * 128 * DDIM);
#pragma unroll
            for (int i = 0; i < 14; ++i) {
                uint32_t d = sb + S_STAGE + (uint32_t)(tid + i * 256) * 16;
                asm volatile("cp.async.cg.shared.global [%0], [%1], 16;"
                             :: "r"(d), "l"(s + tid + i * 256) : "memory");
            }
            asm volatile("cp.async.commit_group;" ::: "memory");
            tl0 = s[3584 + tid];
            tl1 = s[3840 + tid];
        }

        // ---- GEMM1: Z[16 tokens][128 ch] per warp, 3-way bf16 split ----
        float acc[16][4];
#pragma unroll
        for (int t = 0; t < 16; ++t) {
            acc[t][0] = 0.f; acc[t][1] = 0.f; acc[t][2] = 0.f; acc[t][3] = 0.f;
        }
#pragma unroll 1
        for (int s = 0; s < 3; ++s) {
            uint32_t abase = sb + (s == 1 ? S_ALO : S_AHI) + aRow;
            uint32_t wbase = sb + (s == 2 ? S_W1LO : S_W1HI) + bRow;
#pragma unroll 2
            for (int ks = 0; ks < 8; ++ks) {
                uint32_t kc = (uint32_t)(ks * 32);
                uint32_t a0, a1, a2, a3;
                ldm4(abase + ((aCol | kc) ^ xr), a0, a1, a2, a3);
#pragma unroll
                for (int p = 0; p < 8; ++p) {
                    uint32_t v0, v1, v2, v3;
                    ldm4(wbase + (uint32_t)(p * 4096) + ((bCol | kc) ^ xr), v0, v1, v2, v3);
                    mma16816(acc[2 * p],     a0, a1, a2, a3, v0, v1);
                    mma16816(acc[2 * p + 1], a0, a1, a2, a3, v2, v3);
                }
            }
        }

        // ---- intra-warp inclusive scan over the 16-token band ----
#pragma unroll
        for (int t = 0; t < 16; ++t) {
            scan_col(acc[t][0], acc[t][2], lane);
            scan_col(acc[t][1], acc[t][3], lane);
        }
        if (lane >= 28) {
            float* tp = (float*)(sm + S_TOT) + wid * 128 + 2 * four;
#pragma unroll
            for (int t = 0; t < 16; ++t)
                *(float2*)(tp + t * 8) = make_float2(acc[t][2], acc[t][3]);
        }
        __syncthreads();

        // ---- cross-warp offsets: off[w][ch] = cc + prefix(tot) + b1 ----
        if (tid < 128) {
            float a = ((float*)(sm + S_CC))[tid];
            float bv = ((float*)(sm + S_B1))[tid];
            float* tp = (float*)(sm + S_TOT) + tid;
            float* op = (float*)(sm + S_OFF) + tid;
#pragma unroll
            for (int w = 0; w < 8; ++w) {
                op[w * 128] = a + bv;
                a += tp[w * 128];
            }
            ((float*)(sm + S_CC))[tid] = a;
        }
        __syncthreads();

        // ---- apply offsets + leaky, write H1 hi/lo into A tiles ----
        {
            const uint32_t r0 = (uint32_t)(16 * wid + quad);
            const float2* op = (const float2*)(sm + S_OFF) + wid * 64 + four;
#pragma unroll
            for (int t = 0; t < 16; ++t) {
                float2 o = op[t * 4];
                float v0 = lrelu(acc[t][0] + o.x);
                float v1 = lrelu(acc[t][1] + o.y);
                float v2 = lrelu(acc[t][2] + o.x);
                float v3 = lrelu(acc[t][3] + o.y);
                float h0 = bfr(v0), h1 = bfr(v1), h2 = bfr(v2), h3 = bfr(v3);
                uint32_t cb = (uint32_t)(16 * t + 4 * four);
                uint32_t off0 = tswz(r0, cb);
                *(uint32_t*)(sm + S_AHI + off0) = pack2(h0, h1);
                *(uint32_t*)(sm + S_ALO + off0) = pack2(v0 - h0, v1 - h1);
                uint32_t off1 = off0 + 8 * 256;
                *(uint32_t*)(sm + S_AHI + off1) = pack2(h2, h3);
                *(uint32_t*)(sm + S_ALO + off1) = pack2(v2 - h2, v3 - h3);
            }
        }
        __syncthreads();

        // ---- GEMM2: H2[16 tokens][64 ch] per warp ----
        float ac2[8][4];
#pragma unroll
        for (int t = 0; t < 8; ++t) {
            ac2[t][0] = 0.f; ac2[t][1] = 0.f; ac2[t][2] = 0.f; ac2[t][3] = 0.f;
        }
#pragma unroll 1
        for (int s = 0; s < 3; ++s) {
            uint32_t abase = sb + (s == 1 ? S_ALO : S_AHI) + aRow;
            uint32_t wbase = sb + (s == 2 ? S_W2LO : S_W2HI) + bRow;
#pragma unroll 2
            for (int ks = 0; ks < 8; ++ks) {
                uint32_t kc = (uint32_t)(ks * 32);
                uint32_t a0, a1, a2, a3;
                ldm4(abase + ((aCol | kc) ^ xr), a0, a1, a2, a3);
#pragma unroll
                for (int p = 0; p < 4; ++p) {
                    uint32_t v0, v1, v2, v3;
                    ldm4(wbase + (uint32_t)(p * 4096) + ((bCol | kc) ^ xr), v0, v1, v2, v3);
                    mma16816(ac2[2 * p],     a0, a1, a2, a3, v0, v1);
                    mma16816(ac2[2 * p + 1], a0, a1, a2, a3, v2, v3);
                }
            }
        }

        // ---- epilogue: b2 + leaky + dot(W3) + b3 -> out ----
        {
            const float2* b2p = (const float2*)(sm + S_B2) + four;
            const float2* w3p = (const float2*)(sm + S_W3) + four;
            float aL = 0.f, aH = 0.f;
#pragma unroll
            for (int t = 0; t < 8; ++t) {
                float2 bp = b2p[t * 4];
                float2 wp = w3p[t * 4];
                aL += lrelu(ac2[t][0] + bp.x) * wp.x + lrelu(ac2[t][1] + bp.y) * wp.y;
                aH += lrelu(ac2[t][2] + bp.x) * wp.x + lrelu(ac2[t][3] + bp.y) * wp.y;
            }
            aL += __shfl_xor_sync(0xffffffffu, aL, 1);
            aL += __shfl_xor_sync(0xffffffffu, aL, 2);
            aH += __shfl_xor_sync(0xffffffffu, aH, 1);
            aH += __shfl_xor_sync(0xffffffffu, aH, 2);
            if (four == 0) {
                float b3v = *(const float*)(sm + S_B3);
                int g = c * 128 + 16 * wid + quad;
                if (g > 0) out[(size_t)bb * NOUT + g - 1] = aL + b3v;
                out[(size_t)bb * NOUT + g + 7] = aH + b3v;
            }
        }
    }
}

// ---------------------------------------------------------------------------
extern "C" void kernel_launch(void* const* d_in, const int* in_sizes, int n_in,
                              void* d_out, int out_size) {
    const float* x  = (const float*)d_in[0];
    const float* W1 = (const float*)d_in[1];
    const float* b1 = (const float*)d_in[2];
    const float* W2 = (const float*)d_in[3];
    const float* b2 = (const float*)d_in[4];
    const float* W3 = (const float*)d_in[5];
    const float* b3 = (const float*)d_in[6];
    float* out = (float*)d_out;

    static bool attr_done = false;
    if (!attr_done) {
        cudaFuncSetAttribute(fused_kernel,
                             cudaFuncAttributeMaxDynamicSharedMemorySize,
                             SMEM_BYTES);
        attr_done = true;
    }

    fused_kernel<<<BATCH, 256, SMEM_BYTES>>>(x, W1, b1, W2, b2, W3, b3, out);
}

// round 7
// speedup vs baseline: 2.8094x; 1.0995x over previous
#include <cuda_runtime.h>
#include <cuda_bf16.h>
#include <stdint.h>
#include <string.h>

#define BATCH  512
#define NTOK   1024
#define DDIM   128
#define NCHUNK 8
#define NOUT   1023

// ---------------- smem layout (bytes) ----------------
#define S_STAGE 0             // 57344: fp32 x chunk rows 0..111
#define S_AHI   57344         // 32768: A/H1 hi bf16 [128 rows][256B], XOR swizzle
#define S_ALO   90112         // 32768
#define S_W1HI  122880        // 32768
#define S_W1LO  155648        // 32768
#define S_W2HI  188416        // 16384: [64 rows][256B]
#define S_W2LO  204800        // 16384
#define S_TOT   221184        // 1024: band totals [2][128] f32
#define S_OFF   222208        // 1024: band offsets [2][128] f32
#define S_PT    223232        // 2048: epilogue partials [4][128] f32
#define S_B1    225280        // 512
#define S_CC    225792        // 512
#define S_B2    226304        // 256
#define S_W3    226560        // 256
#define S_B3    226816        // 16
#define SMEM_BYTES 226832

static __device__ __forceinline__ uint32_t smem_u32(const void* p) {
    uint32_t a;
    asm("{ .reg .u64 t; cvta.to.shared.u64 t, %1; cvt.u32.u64 %0, t; }"
        : "=r"(a) : "l"(p));
    return a;
}
static __device__ __forceinline__ uint32_t tswz(uint32_t row, uint32_t cb) {
    return row * 256 + (cb ^ ((row & 7) << 4));
}
static __device__ __forceinline__ float bfr(float v) {
    return __bfloat162float(__float2bfloat16(v));
}
static __device__ __forceinline__ uint32_t pack2(float a, float b) {
    __nv_bfloat162 h = __floats2bfloat162_rn(a, b);
    uint32_t u;
    memcpy(&u, &h, 4);
    return u;
}
static __device__ __forceinline__ float lrelu(float v) {
    return v > 0.f ? v : 0.01f * v;
}
static __device__ __forceinline__ void ldm4(uint32_t addr, uint32_t& r0, uint32_t& r1,
                                            uint32_t& r2, uint32_t& r3) {
    asm volatile("ldmatrix.sync.aligned.m8n8.x4.shared.b16 {%0,%1,%2,%3}, [%4];"
                 : "=r"(r0), "=r"(r1), "=r"(r2), "=r"(r3) : "r"(addr));
}
static __device__ __forceinline__ void mma16816(float* d, uint32_t a0, uint32_t a1,
                                                uint32_t a2, uint32_t a3,
                                                uint32_t b0, uint32_t b1) {
    asm volatile("mma.sync.aligned.m16n8k16.row.col.f32.bf16.bf16.f32 "
                 "{%0,%1,%2,%3}, {%4,%5,%6,%7}, {%8,%9}, {%0,%1,%2,%3};"
                 : "+f"(d[0]), "+f"(d[1]), "+f"(d[2]), "+f"(d[3])
                 : "r"(a0), "r"(a1), "r"(a2), "r"(a3), "r"(b0), "r"(b1));
}
static __device__ __forceinline__ void scan_col(float& lo, float& hi, int lane) {
    float o;
    o = __shfl_up_sync(0xffffffffu, lo, 4);  if (lane >= 4)  lo += o;
    o = __shfl_up_sync(0xffffffffu, lo, 8);  if (lane >= 8)  lo += o;
    o = __shfl_up_sync(0xffffffffu, lo, 16); if (lane >= 16) lo += o;
    float tl = __shfl_sync(0xffffffffu, lo, 28 + (lane & 3));
    o = __shfl_up_sync(0xffffffffu, hi, 4);  if (lane >= 4)  hi += o;
    o = __shfl_up_sync(0xffffffffu, hi, 8);  if (lane >= 8)  hi += o;
    o = __shfl_up_sync(0xffffffffu, hi, 16); if (lane >= 16) hi += o;
    hi += tl;
}

__global__ void __launch_bounds__(256, 1)
fused_kernel(const float* __restrict__ x,
             const float* __restrict__ W1, const float* __restrict__ b1,
             const float* __restrict__ W2, const float* __restrict__ b2,
             const float* __restrict__ W3, const float* __restrict__ b3,
             float* __restrict__ out)
{
    extern __shared__ char sm[];
    const uint32_t sb = smem_u32(sm);
    const int tid   = threadIdx.x;
    const int wid   = tid >> 5;
    const int lane  = tid & 31;
    const int quad  = lane >> 2;
    const int four  = lane & 3;
    const int wband = wid >> 2;           // token band: 0 -> rows 0..63, 1 -> 64..127
    const int chgrp = wid & 3;            // channel group
    const int bb    = blockIdx.x;

    const float* xb = x + (size_t)bb * NTOK * DDIM;

    // ---- kick cp.async for chunk 0 (rows 0..111) + tail regs (112..127) ----
    float4 tl0, tl1;
    {
        const float4* s = (const float4*)xb;
#pragma unroll
        for (int i = 0; i < 14; ++i) {
            uint32_t d = sb + S_STAGE + (uint32_t)(tid + i * 256) * 16;
            asm volatile("cp.async.cg.shared.global [%0], [%1], 16;"
                         :: "r"(d), "l"(s + tid + i * 256) : "memory");
        }
        asm volatile("cp.async.commit_group;" ::: "memory");
        tl0 = s[3584 + tid];
        tl1 = s[3840 + tid];
    }

    // ---- stage weights: fp32 -> bf16 hi/lo swizzled tiles ----
    {
        const float2* w1 = (const float2*)W1;
#pragma unroll 4
        for (int i = 0; i < 32; ++i) {
            int idx = tid + i * 256;
            int n = idx >> 6, kp = idx & 63;
            float2 v = w1[idx];
            float hx = bfr(v.x), hy = bfr(v.y);
            uint32_t a = tswz(n, kp * 4);
            *(uint32_t*)(sm + S_W1HI + a) = pack2(hx, hy);
            *(uint32_t*)(sm + S_W1LO + a) = pack2(v.x - hx, v.y - hy);
        }
        const float2* w2 = (const float2*)W2;
#pragma unroll 4
        for (int i = 0; i < 16; ++i) {
            int idx = tid + i * 256;
            int n = idx >> 6, kp = idx & 63;
            float2 v = w2[idx];
            float hx = bfr(v.x), hy = bfr(v.y);
            uint32_t a = tswz(n, kp * 4);
            *(uint32_t*)(sm + S_W2HI + a) = pack2(hx, hy);
            *(uint32_t*)(sm + S_W2LO + a) = pack2(v.x - hx, v.y - hy);
        }
    }
    if (tid < 128) {
        ((float*)(sm + S_B1))[tid] = b1[tid];
        ((float*)(sm + S_CC))[tid] = 0.f;
    } else if (tid < 192) {
        ((float*)(sm + S_B2))[tid - 128] = b2[tid - 128];
    } else {
        ((float*)(sm + S_W3))[tid - 192] = W3[tid - 192];
    }
    if (tid == 0) *(float*)(sm + S_B3) = b3[0];

    // ---- per-lane ldmatrix address pieces ----
    const uint32_t xr   = (uint32_t)((lane & 7) << 4);
    const uint32_t aCol = (uint32_t)(((lane >> 4) & 1) * 16);
    const uint32_t bCol = (uint32_t)(((lane >> 3) & 1) * 16);
    const uint32_t aRowB = (uint32_t)(wband * 64 + (lane & 15)) * 256;   // + t*4096
    const uint32_t bRowB = (uint32_t)((lane & 7) + ((lane >> 4) & 1) * 8) * 256;
    const uint32_t w1Base = sb + S_W1HI + (uint32_t)(chgrp * 32) * 256 + bRowB;  // hi; +32768 for lo
    const uint32_t w2Base = sb + S_W2HI + (uint32_t)(chgrp * 16) * 256 + bRowB;

    for (int c = 0; c < NCHUNK; ++c) {
        asm volatile("cp.async.wait_group 0;" ::: "memory");
        __syncthreads();

        // ---- convert staged chunk -> A hi/lo bf16 ----
        {
            const float2* stg = (const float2*)(sm + S_STAGE);
#pragma unroll 4
            for (int i = 0; i < 28; ++i) {
                int idx = tid + i * 256;
                float2 v = stg[idx];
                int t = idx >> 6, kp = idx & 63;
                float hx = bfr(v.x), hy = bfr(v.y);
                uint32_t a = tswz(t, kp * 4);
                *(uint32_t*)(sm + S_AHI + a) = pack2(hx, hy);
                *(uint32_t*)(sm + S_ALO + a) = pack2(v.x - hx, v.y - hy);
            }
#pragma unroll
            for (int h = 0; h < 2; ++h) {
                float4 v = h ? tl1 : tl0;
                int j = tid + h * 256;
                int off = 14336 + j * 4;
                int r = off >> 7, cb = (off & 127) * 2;
                float h0 = bfr(v.x), h1 = bfr(v.y), h2 = bfr(v.z), h3 = bfr(v.w);
                uint32_t a = tswz(r, (uint32_t)cb);
                *(uint2*)(sm + S_AHI + a) = make_uint2(pack2(h0, h1), pack2(h2, h3));
                *(uint2*)(sm + S_ALO + a) = make_uint2(pack2(v.x - h0, v.y - h1),
                                                       pack2(v.z - h2, v.w - h3));
            }
        }
        __syncthreads();

        // ---- prefetch next chunk ----
        if (c + 1 < NCHUNK) {
            const float4* s = (const float4*)(xb + (size_t)(c + 1) * 128 * DDIM);
#pragma unroll
            for (int i = 0; i < 14; ++i) {
                uint32_t d = sb + S_STAGE + (uint32_t)(tid + i * 256) * 16;
                asm volatile("cp.async.cg.shared.global [%0], [%1], 16;"
                             :: "r"(d), "l"(s + tid + i * 256) : "memory");
            }
            asm volatile("cp.async.commit_group;" ::: "memory");
            tl0 = s[3584 + tid];
            tl1 = s[3840 + tid];
        }

        // ---- GEMM1: warp computes [64 tok][32 ch], fused 3-product split ----
        float acc[4][4][4];
#pragma unroll
        for (int t = 0; t < 4; ++t)
#pragma unroll
            for (int j = 0; j < 4; ++j) {
                acc[t][j][0] = 0.f; acc[t][j][1] = 0.f;
                acc[t][j][2] = 0.f; acc[t][j][3] = 0.f;
            }
        {
            const uint32_t ahiB = sb + S_AHI + aRowB;
            const uint32_t aloB = sb + S_ALO + aRowB;
#pragma unroll 2
            for (int ks = 0; ks < 8; ++ks) {
                uint32_t kc = (uint32_t)(ks * 32);
                uint32_t wk = (bCol | kc) ^ xr;
                uint32_t ak = (aCol | kc) ^ xr;
                uint32_t wh[8], wl[8];
                ldm4(w1Base + wk,                wh[0], wh[1], wh[2], wh[3]);
                ldm4(w1Base + 4096 + wk,         wh[4], wh[5], wh[6], wh[7]);
                ldm4(w1Base + 32768 + wk,        wl[0], wl[1], wl[2], wl[3]);
                ldm4(w1Base + 32768 + 4096 + wk, wl[4], wl[5], wl[6], wl[7]);
#pragma unroll
                for (int t = 0; t < 4; ++t) {
                    uint32_t a0, a1, a2, a3, e0, e1, e2, e3;
                    ldm4(ahiB + (uint32_t)(t * 4096) + ak, a0, a1, a2, a3);
                    ldm4(aloB + (uint32_t)(t * 4096) + ak, e0, e1, e2, e3);
#pragma unroll
                    for (int j = 0; j < 4; ++j) {
                        mma16816(acc[t][j], a0, a1, a2, a3, wh[2 * j], wh[2 * j + 1]);
                        mma16816(acc[t][j], e0, e1, e2, e3, wh[2 * j], wh[2 * j + 1]);
                        mma16816(acc[t][j], a0, a1, a2, a3, wl[2 * j], wl[2 * j + 1]);
                    }
                }
            }
        }

        // ---- scan over the warp's 64-token band (4 tiles, sequential carry) ----
        float ce[4] = {0.f, 0.f, 0.f, 0.f}, co[4] = {0.f, 0.f, 0.f, 0.f};
#pragma unroll
        for (int t = 0; t < 4; ++t) {
#pragma unroll
            for (int j = 0; j < 4; ++j) {
                scan_col(acc[t][j][0], acc[t][j][2], lane);
                scan_col(acc[t][j][1], acc[t][j][3], lane);
                acc[t][j][0] += ce[j]; acc[t][j][2] += ce[j];
                acc[t][j][1] += co[j]; acc[t][j][3] += co[j];
                ce[j] = __shfl_sync(0xffffffffu, acc[t][j][2], 28 + four);
                co[j] = __shfl_sync(0xffffffffu, acc[t][j][3], 28 + four);
            }
        }
        // band totals -> smem
        if (quad == 0) {
            float* tp = (float*)(sm + S_TOT) + wband * 128 + chgrp * 32 + 2 * four;
#pragma unroll
            for (int j = 0; j < 4; ++j)
                *(float2*)(tp + j * 8) = make_float2(ce[j], co[j]);
        }
        __syncthreads();

        // ---- offsets: off[band][ch] = cc + (band ? T0 : 0) + b1 ----
        if (tid < 128) {
            float a  = ((float*)(sm + S_CC))[tid];
            float bv = ((float*)(sm + S_B1))[tid];
            float t0 = ((float*)(sm + S_TOT))[tid];
            float t1 = ((float*)(sm + S_TOT))[128 + tid];
            ((float*)(sm + S_OFF))[tid]       = a + bv;
            ((float*)(sm + S_OFF))[128 + tid] = a + t0 + bv;
            ((float*)(sm + S_CC))[tid]        = a + t0 + t1;
        }
        __syncthreads();

        // ---- apply offsets + leaky, write H1 hi/lo ----
        {
            const float2* op = (const float2*)(sm + S_OFF) + wband * 64 + chgrp * 16 + four;
            const uint32_t r0 = (uint32_t)(wband * 64 + quad);
#pragma unroll
            for (int t = 0; t < 4; ++t) {
#pragma unroll
                for (int j = 0; j < 4; ++j) {
                    float2 o = op[j * 4];
                    float v0 = lrelu(acc[t][j][0] + o.x);
                    float v1 = lrelu(acc[t][j][1] + o.y);
                    float v2 = lrelu(acc[t][j][2] + o.x);
                    float v3 = lrelu(acc[t][j][3] + o.y);
                    float h0 = bfr(v0), h1 = bfr(v1), h2 = bfr(v2), h3 = bfr(v3);
                    uint32_t cb = (uint32_t)(chgrp * 64 + j * 16 + 4 * four);
                    uint32_t a0 = tswz(r0 + (uint32_t)(t * 16), cb);
                    *(uint32_t*)(sm + S_AHI + a0) = pack2(h0, h1);
                    *(uint32_t*)(sm + S_ALO + a0) = pack2(v0 - h0, v1 - h1);
                    uint32_t a1 = a0 + 8 * 256;
                    *(uint32_t*)(sm + S_AHI + a1) = pack2(h2, h3);
                    *(uint32_t*)(sm + S_ALO + a1) = pack2(v2 - h2, v3 - h3);
                }
            }
        }
        __syncthreads();

        // ---- GEMM2: warp computes [64 tok][16 ch] ----
        float ac2[4][2][4];
#pragma unroll
        for (int t = 0; t < 4; ++t)
#pragma unroll
            for (int j = 0; j < 2; ++j) {
                ac2[t][j][0] = 0.f; ac2[t][j][1] = 0.f;
                ac2[t][j][2] = 0.f; ac2[t][j][3] = 0.f;
            }
        {
            const uint32_t ahiB = sb + S_AHI + aRowB;
            const uint32_t aloB = sb + S_ALO + aRowB;
#pragma unroll 2
            for (int ks = 0; ks < 8; ++ks) {
                uint32_t kc = (uint32_t)(ks * 32);
                uint32_t wk = (bCol | kc) ^ xr;
                uint32_t ak = (aCol | kc) ^ xr;
                uint32_t wh[4], wl[4];
                ldm4(w2Base + wk,         wh[0], wh[1], wh[2], wh[3]);
                ldm4(w2Base + 16384 + wk, wl[0], wl[1], wl[2], wl[3]);
#pragma unroll
                for (int t = 0; t < 4; ++t) {
                    uint32_t a0, a1, a2, a3, e0, e1, e2, e3;
                    ldm4(ahiB + (uint32_t)(t * 4096) + ak, a0, a1, a2, a3);
                    ldm4(aloB + (uint32_t)(t * 4096) + ak, e0, e1, e2, e3);
#pragma unroll
                    for (int j = 0; j < 2; ++j) {
                        mma16816(ac2[t][j], a0, a1, a2, a3, wh[2 * j], wh[2 * j + 1]);
                        mma16816(ac2[t][j], e0, e1, e2, e3, wh[2 * j], wh[2 * j + 1]);
                        mma16816(ac2[t][j], a0, a1, a2, a3, wl[2 * j], wl[2 * j + 1]);
                    }
                }
            }
        }

        // ---- epilogue: partial dot over warp's 16 channels -> smem ----
        {
            const float2* b2p = (const float2*)(sm + S_B2) + chgrp * 8 + four;
            const float2* w3p = (const float2*)(sm + S_W3) + chgrp * 8 + four;
            float2 bp0 = b2p[0], bp1 = b2p[4];
            float2 wp0 = w3p[0], wp1 = w3p[4];
            float* pt = (float*)(sm + S_PT) + chgrp * 128 + wband * 64 + quad;
#pragma unroll
            for (int t = 0; t < 4; ++t) {
                float pl = lrelu(ac2[t][0][0] + bp0.x) * wp0.x
                         + lrelu(ac2[t][0][1] + bp0.y) * wp0.y
                         + lrelu(ac2[t][1][0] + bp1.x) * wp1.x
                         + lrelu(ac2[t][1][1] + bp1.y) * wp1.y;
                float ph = lrelu(ac2[t][0][2] + bp0.x) * wp0.x
                         + lrelu(ac2[t][0][3] + bp0.y) * wp0.y
                         + lrelu(ac2[t][1][2] + bp1.x) * wp1.x
                         + lrelu(ac2[t][1][3] + bp1.y) * wp1.y;
                pl += __shfl_xor_sync(0xffffffffu, pl, 1);
                pl += __shfl_xor_sync(0xffffffffu, pl, 2);
                ph += __shfl_xor_sync(0xffffffffu, ph, 1);
                ph += __shfl_xor_sync(0xffffffffu, ph, 2);
                if (four == 0) {
                    pt[t * 16] = pl;
                    pt[t * 16 + 8] = ph;
                }
            }
        }
        __syncthreads();

        // ---- combine partials + b3 -> out ----
        if (tid < 128) {
            const float* pt = (const float*)(sm + S_PT);
            float s = pt[tid] + pt[128 + tid] + pt[256 + tid] + pt[384 + tid]
                    + *(const float*)(sm + S_B3);
            int g = c * 128 + tid;
            if (g > 0) out[(size_t)bb * NOUT + g - 1] = s;
        }
    }
}

// ---------------------------------------------------------------------------
extern "C" void kernel_launch(void* const* d_in, const int* in_sizes, int n_in,
                              void* d_out, int out_size) {
    const float* x  = (const float*)d_in[0];
    const float* W1 = (const float*)d_in[1];
    const float* b1 = (const float*)d_in[2];
    const float* W2 = (const float*)d_in[3];
    const float* b2 = (const float*)d_in[4];
    const float* W3 = (const float*)d_in[5];
    const float* b3 = (const float*)d_in[6];
    float* out = (float*)d_out;

    static bool attr_done = false;
    if (!attr_done) {
        cudaFuncSetAttribute(fused_kernel,
                             cudaFuncAttributeMaxDynamicSharedMemorySize,
                             SMEM_BYTES);
        attr_done = true;
    }

    fused_kernel<<<BATCH, 256, SMEM_BYTES>>>(x, W1, b1, W2, b2, W3, b3, out);
}

// round 8
// speedup vs baseline: 3.2101x; 1.1426x over previous
#include <cuda_runtime.h>
#include <cuda_bf16.h>
#include <stdint.h>
#include <string.h>

#define BATCH  512
#define NTOK   1024
#define DDIM   128
#define NCHUNK 8
#define NOUT   1023
#define NTHR   512

// ---------------- smem layout (bytes) ----------------
#define S_STAGE 0             // 57344: fp32 x chunk rows 0..111
#define S_AHI   57344         // 32768: A/H1 hi bf16 [128 rows][256B], XOR swizzle
#define S_ALO   90112         // 32768
#define S_W1HI  122880        // 32768
#define S_W1LO  155648        // 32768
#define S_W2HI  188416        // 16384: [64 rows][256B]
#define S_W2LO  204800        // 16384
#define S_TOT   221184        // 2048: band totals [4][128] f32
#define S_OFF   223232        // 2048: band offsets [4][128] f32
#define S_PT    225280        // 2048: epilogue partials [4][128] f32
#define S_B1    227328        // 512
#define S_CC    227840        // 512
#define S_B2    228352        // 256
#define S_W3    228608        // 256
#define S_B3    228864        // 16
#define SMEM_BYTES 228880

static __device__ __forceinline__ uint32_t smem_u32(const void* p) {
    uint32_t a;
    asm("{ .reg .u64 t; cvta.to.shared.u64 t, %1; cvt.u32.u64 %0, t; }"
        : "=r"(a) : "l"(p));
    return a;
}
static __device__ __forceinline__ uint32_t tswz(uint32_t row, uint32_t cb) {
    return row * 256 + (cb ^ ((row & 7) << 4));
}
static __device__ __forceinline__ float bfr(float v) {
    return __bfloat162float(__float2bfloat16(v));
}
static __device__ __forceinline__ uint32_t pack2(float a, float b) {
    __nv_bfloat162 h = __floats2bfloat162_rn(a, b);
    uint32_t u;
    memcpy(&u, &h, 4);
    return u;
}
static __device__ __forceinline__ float lrelu(float v) {
    return v > 0.f ? v : 0.01f * v;
}
static __device__ __forceinline__ void ldm4(uint32_t addr, uint32_t& r0, uint32_t& r1,
                                            uint32_t& r2, uint32_t& r3) {
    asm volatile("ldmatrix.sync.aligned.m8n8.x4.shared.b16 {%0,%1,%2,%3}, [%4];"
                 : "=r"(r0), "=r"(r1), "=r"(r2), "=r"(r3) : "r"(addr));
}
static __device__ __forceinline__ void mma16816(float* d, uint32_t a0, uint32_t a1,
                                                uint32_t a2, uint32_t a3,
                                                uint32_t b0, uint32_t b1) {
    asm volatile("mma.sync.aligned.m16n8k16.row.col.f32.bf16.bf16.f32 "
                 "{%0,%1,%2,%3}, {%4,%5,%6,%7}, {%8,%9}, {%0,%1,%2,%3};"
                 : "+f"(d[0]), "+f"(d[1]), "+f"(d[2]), "+f"(d[3])
                 : "r"(a0), "r"(a1), "r"(a2), "r"(a3), "r"(b0), "r"(b1));
}
static __device__ __forceinline__ void scan_col(float& lo, float& hi, int lane) {
    float o;
    o = __shfl_up_sync(0xffffffffu, lo, 4);  if (lane >= 4)  lo += o;
    o = __shfl_up_sync(0xffffffffu, lo, 8);  if (lane >= 8)  lo += o;
    o = __shfl_up_sync(0xffffffffu, lo, 16); if (lane >= 16) lo += o;
    float tl = __shfl_sync(0xffffffffu, lo, 28 + (lane & 3));
    o = __shfl_up_sync(0xffffffffu, hi, 4);  if (lane >= 4)  hi += o;
    o = __shfl_up_sync(0xffffffffu, hi, 8);  if (lane >= 8)  hi += o;
    o = __shfl_up_sync(0xffffffffu, hi, 16); if (lane >= 16) hi += o;
    hi += tl;
}

__global__ void __launch_bounds__(NTHR, 1)
fused_kernel(const float* __restrict__ x,
             const float* __restrict__ W1, const float* __restrict__ b1,
             const float* __restrict__ W2, const float* __restrict__ b2,
             const float* __restrict__ W3, const float* __restrict__ b3,
             float* __restrict__ out)
{
    extern __shared__ char sm[];
    const uint32_t sb = smem_u32(sm);
    const int tid   = threadIdx.x;
    const int wid   = tid >> 5;
    const int lane  = tid & 31;
    const int quad  = lane >> 2;
    const int four  = lane & 3;
    const int wband = wid >> 2;           // token band: rows wband*32 .. +31
    const int chgrp = wid & 3;            // channel group
    const int bb    = blockIdx.x;

    const float* xb = x + (size_t)bb * NTOK * DDIM;

    // ---- kick cp.async for chunk 0 (rows 0..111) + tail regs (112..127) ----
    float4 tl0;
    {
        const float4* s = (const float4*)xb;
#pragma unroll
        for (int i = 0; i < 7; ++i) {
            uint32_t d = sb + S_STAGE + (uint32_t)(tid + i * NTHR) * 16;
            asm volatile("cp.async.cg.shared.global [%0], [%1], 16;"
                         :: "r"(d), "l"(s + tid + i * NTHR) : "memory");
        }
        asm volatile("cp.async.commit_group;" ::: "memory");
        tl0 = s[3584 + tid];
    }

    // ---- stage weights: fp32 -> bf16 hi/lo swizzled tiles ----
    {
        const float2* w1 = (const float2*)W1;
#pragma unroll 4
        for (int i = 0; i < 16; ++i) {
            int idx = tid + i * NTHR;
            int n = idx >> 6, kp = idx & 63;
            float2 v = w1[idx];
            float hx = bfr(v.x), hy = bfr(v.y);
            uint32_t a = tswz(n, kp * 4);
            *(uint32_t*)(sm + S_W1HI + a) = pack2(hx, hy);
            *(uint32_t*)(sm + S_W1LO + a) = pack2(v.x - hx, v.y - hy);
        }
        const float2* w2 = (const float2*)W2;
#pragma unroll 4
        for (int i = 0; i < 8; ++i) {
            int idx = tid + i * NTHR;
            int n = idx >> 6, kp = idx & 63;
            float2 v = w2[idx];
            float hx = bfr(v.x), hy = bfr(v.y);
            uint32_t a = tswz(n, kp * 4);
            *(uint32_t*)(sm + S_W2HI + a) = pack2(hx, hy);
            *(uint32_t*)(sm + S_W2LO + a) = pack2(v.x - hx, v.y - hy);
        }
    }
    if (tid < 128) {
        ((float*)(sm + S_B1))[tid] = b1[tid];
        ((float*)(sm + S_CC))[tid] = 0.f;
    } else if (tid < 192) {
        ((float*)(sm + S_B2))[tid - 128] = b2[tid - 128];
    } else if (tid < 256) {
        ((float*)(sm + S_W3))[tid - 192] = W3[tid - 192];
    }
    if (tid == 0) *(float*)(sm + S_B3) = b3[0];

    // ---- per-lane ldmatrix address pieces ----
    const uint32_t xr   = (uint32_t)((lane & 7) << 4);
    const uint32_t aCol = (uint32_t)(((lane >> 4) & 1) * 16);
    const uint32_t bCol = (uint32_t)(((lane >> 3) & 1) * 16);
    const uint32_t aRowB = (uint32_t)(wband * 32 + (lane & 15)) * 256;   // + t*4096
    const uint32_t bRowB = (uint32_t)((lane & 7) + ((lane >> 4) & 1) * 8) * 256;
    const uint32_t w1Base = sb + S_W1HI + (uint32_t)(chgrp * 32) * 256 + bRowB;  // hi; +32768 lo
    const uint32_t w2Base = sb + S_W2HI + (uint32_t)(chgrp * 16) * 256 + bRowB;  // hi; +16384 lo

    for (int c = 0; c < NCHUNK; ++c) {
        asm volatile("cp.async.wait_group 0;" ::: "memory");
        __syncthreads();

        // ---- convert staged chunk -> A hi/lo bf16 ----
        {
            const float2* stg = (const float2*)(sm + S_STAGE);
#pragma unroll 4
            for (int i = 0; i < 14; ++i) {
                int idx = tid + i * NTHR;
                float2 v = stg[idx];
                int t = idx >> 6, kp = idx & 63;
                float hx = bfr(v.x), hy = bfr(v.y);
                uint32_t a = tswz(t, kp * 4);
                *(uint32_t*)(sm + S_AHI + a) = pack2(hx, hy);
                *(uint32_t*)(sm + S_ALO + a) = pack2(v.x - hx, v.y - hy);
            }
            // tail rows 112..127 from registers (one float4 per thread)
            {
                float4 v = tl0;
                int off = 14336 + tid * 4;
                int r = off >> 7, cb = (off & 127) * 2;
                float h0 = bfr(v.x), h1 = bfr(v.y), h2 = bfr(v.z), h3 = bfr(v.w);
                uint32_t a = tswz(r, (uint32_t)cb);
                *(uint2*)(sm + S_AHI + a) = make_uint2(pack2(h0, h1), pack2(h2, h3));
                *(uint2*)(sm + S_ALO + a) = make_uint2(pack2(v.x - h0, v.y - h1),
                                                       pack2(v.z - h2, v.w - h3));
            }
        }
        __syncthreads();

        // ---- prefetch next chunk ----
        if (c + 1 < NCHUNK) {
            const float4* s = (const float4*)(xb + (size_t)(c + 1) * 128 * DDIM);
#pragma unroll
            for (int i = 0; i < 7; ++i) {
                uint32_t d = sb + S_STAGE + (uint32_t)(tid + i * NTHR) * 16;
                asm volatile("cp.async.cg.shared.global [%0], [%1], 16;"
                             :: "r"(d), "l"(s + tid + i * NTHR) : "memory");
            }
            asm volatile("cp.async.commit_group;" ::: "memory");
            tl0 = s[3584 + tid];
        }

        // ---- GEMM1: warp computes [32 tok][32 ch], fused 3-product split ----
        float acc[2][4][4];
#pragma unroll
        for (int t = 0; t < 2; ++t)
#pragma unroll
            for (int j = 0; j < 4; ++j) {
                acc[t][j][0] = 0.f; acc[t][j][1] = 0.f;
                acc[t][j][2] = 0.f; acc[t][j][3] = 0.f;
            }
        {
            const uint32_t ahiB = sb + S_AHI + aRowB;
            const uint32_t aloB = sb + S_ALO + aRowB;
#pragma unroll 2
            for (int ks = 0; ks < 8; ++ks) {
                uint32_t kc = (uint32_t)(ks * 32);
                uint32_t wk = (bCol | kc) ^ xr;
                uint32_t ak = (aCol | kc) ^ xr;
                uint32_t wh[8], wl[8];
                ldm4(w1Base + wk,                wh[0], wh[1], wh[2], wh[3]);
                ldm4(w1Base + 4096 + wk,         wh[4], wh[5], wh[6], wh[7]);
                ldm4(w1Base + 32768 + wk,        wl[0], wl[1], wl[2], wl[3]);
                ldm4(w1Base + 32768 + 4096 + wk, wl[4], wl[5], wl[6], wl[7]);
#pragma unroll
                for (int t = 0; t < 2; ++t) {
                    uint32_t a0, a1, a2, a3, e0, e1, e2, e3;
                    ldm4(ahiB + (uint32_t)(t * 4096) + ak, a0, a1, a2, a3);
                    ldm4(aloB + (uint32_t)(t * 4096) + ak, e0, e1, e2, e3);
#pragma unroll
                    for (int j = 0; j < 4; ++j) {
                        mma16816(acc[t][j], a0, a1, a2, a3, wh[2 * j], wh[2 * j + 1]);
                        mma16816(acc[t][j], e0, e1, e2, e3, wh[2 * j], wh[2 * j + 1]);
                        mma16816(acc[t][j], a0, a1, a2, a3, wl[2 * j], wl[2 * j + 1]);
                    }
                }
            }
        }

        // ---- scan over the warp's 32-token band (2 tiles, sequential carry) ----
        float ce[4] = {0.f, 0.f, 0.f, 0.f}, co[4] = {0.f, 0.f, 0.f, 0.f};
#pragma unroll
        for (int t = 0; t < 2; ++t) {
#pragma unroll
            for (int j = 0; j < 4; ++j) {
                scan_col(acc[t][j][0], acc[t][j][2], lane);
                scan_col(acc[t][j][1], acc[t][j][3], lane);
                acc[t][j][0] += ce[j]; acc[t][j][2] += ce[j];
                acc[t][j][1] += co[j]; acc[t][j][3] += co[j];
                ce[j] = __shfl_sync(0xffffffffu, acc[t][j][2], 28 + four);
                co[j] = __shfl_sync(0xffffffffu, acc[t][j][3], 28 + four);
            }
        }
        // band totals -> smem
        if (quad == 0) {
            float* tp = (float*)(sm + S_TOT) + wband * 128 + chgrp * 32 + 2 * four;
#pragma unroll
            for (int j = 0; j < 4; ++j)
                *(float2*)(tp + j * 8) = make_float2(ce[j], co[j]);
        }
        __syncthreads();

        // ---- offsets: off[band][ch] = cc + prefix(tot) + b1 ----
        if (tid < 128) {
            float a  = ((float*)(sm + S_CC))[tid];
            float bv = ((float*)(sm + S_B1))[tid];
#pragma unroll
            for (int w = 0; w < 4; ++w) {
                ((float*)(sm + S_OFF))[w * 128 + tid] = a + bv;
                a += ((float*)(sm + S_TOT))[w * 128 + tid];
            }
            ((float*)(sm + S_CC))[tid] = a;
        }
        __syncthreads();

        // ---- apply offsets + leaky, write H1 hi/lo ----
        {
            const float2* op = (const float2*)(sm + S_OFF) + wband * 64 + chgrp * 16 + four;
            const uint32_t r0 = (uint32_t)(wband * 32 + quad);
#pragma unroll
            for (int t = 0; t < 2; ++t) {
#pragma unroll
                for (int j = 0; j < 4; ++j) {
                    float2 o = op[j * 4];
                    float v0 = lrelu(acc[t][j][0] + o.x);
                    float v1 = lrelu(acc[t][j][1] + o.y);
                    float v2 = lrelu(acc[t][j][2] + o.x);
                    float v3 = lrelu(acc[t][j][3] + o.y);
                    float h0 = bfr(v0), h1 = bfr(v1), h2 = bfr(v2), h3 = bfr(v3);
                    uint32_t cb = (uint32_t)(chgrp * 64 + j * 16 + 4 * four);
                    uint32_t a0 = tswz(r0 + (uint32_t)(t * 16), cb);
                    *(uint32_t*)(sm + S_AHI + a0) = pack2(h0, h1);
                    *(uint32_t*)(sm + S_ALO + a0) = pack2(v0 - h0, v1 - h1);
                    uint32_t a1 = a0 + 8 * 256;
                    *(uint32_t*)(sm + S_AHI + a1) = pack2(h2, h3);
                    *(uint32_t*)(sm + S_ALO + a1) = pack2(v2 - h2, v3 - h3);
                }
            }
        }
        __syncthreads();

        // ---- GEMM2: warp computes [32 tok][16 ch] ----
        float ac2[2][2][4];
#pragma unroll
        for (int t = 0; t < 2; ++t)
#pragma unroll
            for (int j = 0; j < 2; ++j) {
                ac2[t][j][0] = 0.f; ac2[t][j][1] = 0.f;
                ac2[t][j][2] = 0.f; ac2[t][j][3] = 0.f;
            }
        {
            const uint32_t ahiB = sb + S_AHI + aRowB;
            const uint32_t aloB = sb + S_ALO + aRowB;
#pragma unroll 2
            for (int ks = 0; ks < 8; ++ks) {
                uint32_t kc = (uint32_t)(ks * 32);
                uint32_t wk = (bCol | kc) ^ xr;
                uint32_t ak = (aCol | kc) ^ xr;
                uint32_t wh[4], wl[4];
                ldm4(w2Base + wk,         wh[0], wh[1], wh[2], wh[3]);
                ldm4(w2Base + 16384 + wk, wl[0], wl[1], wl[2], wl[3]);
#pragma unroll
                for (int t = 0; t < 2; ++t) {
                    uint32_t a0, a1, a2, a3, e0, e1, e2, e3;
                    ldm4(ahiB + (uint32_t)(t * 4096) + ak, a0, a1, a2, a3);
                    ldm4(aloB + (uint32_t)(t * 4096) + ak, e0, e1, e2, e3);
#pragma unroll
                    for (int j = 0; j < 2; ++j) {
                        mma16816(ac2[t][j], a0, a1, a2, a3, wh[2 * j], wh[2 * j + 1]);
                        mma16816(ac2[t][j], e0, e1, e2, e3, wh[2 * j], wh[2 * j + 1]);
                        mma16816(ac2[t][j], a0, a1, a2, a3, wl[2 * j], wl[2 * j + 1]);
                    }
                }
            }
        }

        // ---- epilogue: partial dot over warp's 16 channels -> smem ----
        {
            const float2* b2p = (const float2*)(sm + S_B2) + chgrp * 8 + four;
            const float2* w3p = (const float2*)(sm + S_W3) + chgrp * 8 + four;
            float2 bp0 = b2p[0], bp1 = b2p[4];
            float2 wp0 = w3p[0], wp1 = w3p[4];
            float* pt = (float*)(sm + S_PT) + chgrp * 128 + wband * 32 + quad;
#pragma unroll
            for (int t = 0; t < 2; ++t) {
                float pl = lrelu(ac2[t][0][0] + bp0.x) * wp0.x
                         + lrelu(ac2[t][0][1] + bp0.y) * wp0.y
                         + lrelu(ac2[t][1][0] + bp1.x) * wp1.x
                         + lrelu(ac2[t][1][1] + bp1.y) * wp1.y;
                float ph = lrelu(ac2[t][0][2] + bp0.x) * wp0.x
                         + lrelu(ac2[t][0][3] + bp0.y) * wp0.y
                         + lrelu(ac2[t][1][2] + bp1.x) * wp1.x
                         + lrelu(ac2[t][1][3] + bp1.y) * wp1.y;
                pl += __shfl_xor_sync(0xffffffffu, pl, 1);
                pl += __shfl_xor_sync(0xffffffffu, pl, 2);
                ph += __shfl_xor_sync(0xffffffffu, ph, 1);
                ph += __shfl_xor_sync(0xffffffffu, ph, 2);
                if (four == 0) {
                    pt[t * 16] = pl;
                    pt[t * 16 + 8] = ph;
                }
            }
        }
        __syncthreads();

        // ---- combine partials + b3 -> out ----
        if (tid < 128) {
            const float* pt = (const float*)(sm + S_PT);
            float s = pt[tid] + pt[128 + tid] + pt[256 + tid] + pt[384 + tid]
                    + *(const float*)(sm + S_B3);
            int g = c * 128 + tid;
            if (g > 0) out[(size_t)bb * NOUT + g - 1] = s;
        }
    }
}

// ---------------------------------------------------------------------------
extern "C" void kernel_launch(void* const* d_in, const int* in_sizes, int n_in,
                              void* d_out, int out_size) {
    const float* x  = (const float*)d_in[0];
    const float* W1 = (const float*)d_in[1];
    const float* b1 = (const float*)d_in[2];
    const float* W2 = (const float*)d_in[3];
    const float* b2 = (const float*)d_in[4];
    const float* W3 = (const float*)d_in[5];
    const float* b3 = (const float*)d_in[6];
    float* out = (float*)d_out;

    static bool attr_done = false;
    if (!attr_done) {
        cudaFuncSetAttribute(fused_kernel,
                             cudaFuncAttributeMaxDynamicSharedMemorySize,
                             SMEM_BYTES);
        attr_done = true;
    }

    fused_kernel<<<BATCH, NTHR, SMEM_BYTES>>>(x, W1, b1, W2, b2, W3, b3, out);
}